// round 2
// baseline (speedup 1.0000x reference)
#include <cuda_runtime.h>
#include <math.h>

// Problem dimensions (fixed by the dataset)
#define Bsz   8
#define Tt    16
#define NCc   128
#define NcelL 64
#define DnL   64
#define Aa    4
#define HmL   128

// Pre-transposed MLP weights (written by a tiny setup kernel each launch).
// g_w1T[d][h] = msg_w1[h][d]   (so layer-1 inner-d loop reads contiguous rows)
// g_w2T[h][d] = msg_w2[d][h]   (so layer-2 inner-h loop reads contiguous rows)
__device__ float g_w1T[DnL * HmL];
__device__ float g_w2T[HmL * DnL];

__global__ void mg_transpose(const float* __restrict__ w1,
                             const float* __restrict__ w2) {
    int tid = blockIdx.x * blockDim.x + threadIdx.x;
    if (tid < HmL * DnL) {
        int h = tid / DnL, d = tid % DnL;       // w1 is [Hm][Dn]
        g_w1T[d * HmL + h] = w1[tid];
        int d2 = tid / HmL, h2 = tid % HmL;     // w2 is [Dn][Hm]
        g_w2T[h2 * DnL + d2] = w2[tid];
    }
}

// One CTA per (b, c) pair. State (h, W, hebbian) lives in shared memory for
// the whole T-loop. 256 threads.
__global__ __launch_bounds__(256, 2)
void mg_main(const float* __restrict__ x,     const float* __restrict__ h0,
             const float* __restrict__ W0,    const float* __restrict__ heb0,
             const float* __restrict__ nid,
             const float* __restrict__ injw,  const float* __restrict__ injb,
             const float* __restrict__ b1g,   const float* __restrict__ b2g,
             const float* __restrict__ wdl,   const float* __restrict__ dgl,
             const float* __restrict__ hdl,
             const int*   __restrict__ ipi,   const int*   __restrict__ opi,
             float* __restrict__ out) {
    extern __shared__ float sm[];
    float* sH    = sm;               // 4096  h (in-place: h -> h_in -> h_new)
    float* sW    = sH    + 4096;     // 4096  slow weights
    float* sHeb  = sW    + 4096;     // 4096  hebbian
    float* sM    = sHeb  + 4096;     // 4096  matmul-1 output
    float* sBig  = sM    + 4096;     // 8192  Wh (first 4096) then MLP hidden t
    float* sX    = sBig  + 8192;     // 64
    float* sInj  = sX    + 64;       // 256
    float* sInjB = sInj  + 256;      // 256
    float* sGam  = sInjB + 256;      // 64
    float* sHg   = sGam  + 64;       // 64
    float* sWg   = sHg   + 64;       // 64
    float* sB1   = sWg   + 64;       // 128
    float* sB2   = sB1   + 128;      // 64
    __shared__ int sIp[4], sOp[4];

    const int tid = threadIdx.x;
    const int c   = blockIdx.x / Bsz;     // c-major: co-resident CTAs share cell params in L2
    const int b   = blockIdx.x % Bsz;
    const int base = (b * NCc + c) * (NcelL * DnL);

    // ---- one-time setup ----
    if (tid < 64) {
        sGam[tid] = 0.5f / (1.0f + expf(-dgl[c * 64 + tid]));
        sHg[tid]  = 0.5f / (1.0f + expf(-hdl[c * 64 + tid]));
        sWg[tid]  = 0.5f / (1.0f + expf(-wdl[c * 64 + tid]));
        sB2[tid]  = b2g[tid];
    }
    if (tid < 128) sB1[tid] = b1g[tid];
    sInjB[tid] = injb[c * 256 + tid];
    if (tid < 4) { sIp[tid] = ipi[c * 4 + tid]; sOp[tid] = opi[c * 4 + tid]; }
    for (int i = tid; i < 4096; i += 256) {
        sH[i]   = h0[base + i];
        sW[i]   = W0[base + i];
        sHeb[i] = heb0[base + i];
    }
    __syncthreads();

    const int ig = tid >> 4;        // 0..15 (row-tile group)
    const int lg = tid & 15;        // 0..15 (col-tile group)
    const int i0 = ig * 4;

    for (int t = 0; t < Tt; ++t) {
        // ---- load x_t ----
        if (tid < 64) sX[tid] = x[((b * Tt + t) * NCc + c) * 64 + tid];
        __syncthreads();

        // ---- inject matvec (thread k = tid) + Wh = W + heb ----
        {
            const float4* wrow = reinterpret_cast<const float4*>(injw + (c * 256 + tid) * 64);
            float acc = sInjB[tid];
            #pragma unroll
            for (int q = 0; q < 16; q++) {
                float4 w  = __ldg(wrow + q);
                float4 xv = *reinterpret_cast<const float4*>(sX + 4 * q);
                acc = fmaf(w.x, xv.x, acc);
                acc = fmaf(w.y, xv.y, acc);
                acc = fmaf(w.z, xv.z, acc);
                acc = fmaf(w.w, xv.w, acc);
            }
            sInj[tid] = acc;
        }
        for (int i = tid; i < 4096; i += 256) sBig[i] = sW[i] + sHeb[i];
        __syncthreads();

        // ---- scatter-add onto input ports (serial per d-thread: handles dup ports) ----
        if (tid < 64) {
            #pragma unroll
            for (int a = 0; a < 4; a++) sH[sIp[a] * 64 + tid] += sInj[a * 64 + tid];
        }
        __syncthreads();

        // ---- matmul-1: m[i,d] = sum_j Wh[i,j] * h_in[j,d]  (4x4 tile/thread) ----
        {
            const int d0 = lg * 4;
            float acc[4][4];
            #pragma unroll
            for (int ii = 0; ii < 4; ii++)
                #pragma unroll
                for (int dd = 0; dd < 4; dd++) acc[ii][dd] = 0.0f;

            for (int j = 0; j < 64; j += 4) {
                float4 wr[4], hv[4];
                #pragma unroll
                for (int ii = 0; ii < 4; ii++)
                    wr[ii] = *reinterpret_cast<const float4*>(sBig + (i0 + ii) * 64 + j);
                #pragma unroll
                for (int jj = 0; jj < 4; jj++)
                    hv[jj] = *reinterpret_cast<const float4*>(sH + (j + jj) * 64 + d0);
                #pragma unroll
                for (int ii = 0; ii < 4; ii++) {
                    acc[ii][0] = fmaf(wr[ii].x, hv[0].x, acc[ii][0]);
                    acc[ii][1] = fmaf(wr[ii].x, hv[0].y, acc[ii][1]);
                    acc[ii][2] = fmaf(wr[ii].x, hv[0].z, acc[ii][2]);
                    acc[ii][3] = fmaf(wr[ii].x, hv[0].w, acc[ii][3]);
                    acc[ii][0] = fmaf(wr[ii].y, hv[1].x, acc[ii][0]);
                    acc[ii][1] = fmaf(wr[ii].y, hv[1].y, acc[ii][1]);
                    acc[ii][2] = fmaf(wr[ii].y, hv[1].z, acc[ii][2]);
                    acc[ii][3] = fmaf(wr[ii].y, hv[1].w, acc[ii][3]);
                    acc[ii][0] = fmaf(wr[ii].z, hv[2].x, acc[ii][0]);
                    acc[ii][1] = fmaf(wr[ii].z, hv[2].y, acc[ii][1]);
                    acc[ii][2] = fmaf(wr[ii].z, hv[2].z, acc[ii][2]);
                    acc[ii][3] = fmaf(wr[ii].z, hv[2].w, acc[ii][3]);
                    acc[ii][0] = fmaf(wr[ii].w, hv[3].x, acc[ii][0]);
                    acc[ii][1] = fmaf(wr[ii].w, hv[3].y, acc[ii][1]);
                    acc[ii][2] = fmaf(wr[ii].w, hv[3].z, acc[ii][2]);
                    acc[ii][3] = fmaf(wr[ii].w, hv[3].w, acc[ii][3]);
                }
            }
            #pragma unroll
            for (int ii = 0; ii < 4; ii++) {
                float4 v = make_float4(acc[ii][0], acc[ii][1], acc[ii][2], acc[ii][3]);
                *reinterpret_cast<float4*>(sM + (i0 + ii) * 64 + d0) = v;
            }
        }
        __syncthreads();

        // ---- MLP layer 1: t[i,h] = tanh(sum_d m[i,d]*w1T[d,h] + b1[h]), 4x8 tile ----
        {
            const int h0i = lg * 8;
            float acc[4][8];
            #pragma unroll
            for (int ii = 0; ii < 4; ii++)
                #pragma unroll
                for (int hh = 0; hh < 8; hh++) acc[ii][hh] = 0.0f;

            for (int d = 0; d < 64; d += 2) {
                float2 mv[4];
                #pragma unroll
                for (int ii = 0; ii < 4; ii++)
                    mv[ii] = *reinterpret_cast<const float2*>(sM + (i0 + ii) * 64 + d);
                float4 wa0 = __ldg(reinterpret_cast<const float4*>(g_w1T + d * HmL + h0i));
                float4 wb0 = __ldg(reinterpret_cast<const float4*>(g_w1T + d * HmL + h0i + 4));
                float4 wa1 = __ldg(reinterpret_cast<const float4*>(g_w1T + (d + 1) * HmL + h0i));
                float4 wb1 = __ldg(reinterpret_cast<const float4*>(g_w1T + (d + 1) * HmL + h0i + 4));
                #pragma unroll
                for (int ii = 0; ii < 4; ii++) {
                    float m0 = mv[ii].x, m1 = mv[ii].y;
                    acc[ii][0] = fmaf(m0, wa0.x, acc[ii][0]);
                    acc[ii][1] = fmaf(m0, wa0.y, acc[ii][1]);
                    acc[ii][2] = fmaf(m0, wa0.z, acc[ii][2]);
                    acc[ii][3] = fmaf(m0, wa0.w, acc[ii][3]);
                    acc[ii][4] = fmaf(m0, wb0.x, acc[ii][4]);
                    acc[ii][5] = fmaf(m0, wb0.y, acc[ii][5]);
                    acc[ii][6] = fmaf(m0, wb0.z, acc[ii][6]);
                    acc[ii][7] = fmaf(m0, wb0.w, acc[ii][7]);
                    acc[ii][0] = fmaf(m1, wa1.x, acc[ii][0]);
                    acc[ii][1] = fmaf(m1, wa1.y, acc[ii][1]);
                    acc[ii][2] = fmaf(m1, wa1.z, acc[ii][2]);
                    acc[ii][3] = fmaf(m1, wa1.w, acc[ii][3]);
                    acc[ii][4] = fmaf(m1, wb1.x, acc[ii][4]);
                    acc[ii][5] = fmaf(m1, wb1.y, acc[ii][5]);
                    acc[ii][6] = fmaf(m1, wb1.z, acc[ii][6]);
                    acc[ii][7] = fmaf(m1, wb1.w, acc[ii][7]);
                }
            }
            #pragma unroll
            for (int ii = 0; ii < 4; ii++) {
                #pragma unroll
                for (int hh = 0; hh < 8; hh++)
                    acc[ii][hh] = tanhf(acc[ii][hh] + sB1[h0i + hh]);
                float4 v0 = make_float4(acc[ii][0], acc[ii][1], acc[ii][2], acc[ii][3]);
                float4 v1 = make_float4(acc[ii][4], acc[ii][5], acc[ii][6], acc[ii][7]);
                *reinterpret_cast<float4*>(sBig + (i0 + ii) * 128 + h0i)     = v0;
                *reinterpret_cast<float4*>(sBig + (i0 + ii) * 128 + h0i + 4) = v1;
            }
        }
        __syncthreads();

        // ---- MLP layer 2 + gated state update: 4x4 tile/thread, sH in place ----
        {
            const int d0 = lg * 4;
            float acc[4][4];
            #pragma unroll
            for (int ii = 0; ii < 4; ii++)
                #pragma unroll
                for (int dd = 0; dd < 4; dd++) acc[ii][dd] = 0.0f;

            for (int h = 0; h < 128; h += 4) {
                float4 tv[4], wv[4];
                #pragma unroll
                for (int ii = 0; ii < 4; ii++)
                    tv[ii] = *reinterpret_cast<const float4*>(sBig + (i0 + ii) * 128 + h);
                #pragma unroll
                for (int hh = 0; hh < 4; hh++)
                    wv[hh] = __ldg(reinterpret_cast<const float4*>(g_w2T + (h + hh) * DnL + d0));
                #pragma unroll
                for (int ii = 0; ii < 4; ii++) {
                    acc[ii][0] = fmaf(tv[ii].x, wv[0].x, acc[ii][0]);
                    acc[ii][1] = fmaf(tv[ii].x, wv[0].y, acc[ii][1]);
                    acc[ii][2] = fmaf(tv[ii].x, wv[0].z, acc[ii][2]);
                    acc[ii][3] = fmaf(tv[ii].x, wv[0].w, acc[ii][3]);
                    acc[ii][0] = fmaf(tv[ii].y, wv[1].x, acc[ii][0]);
                    acc[ii][1] = fmaf(tv[ii].y, wv[1].y, acc[ii][1]);
                    acc[ii][2] = fmaf(tv[ii].y, wv[1].z, acc[ii][2]);
                    acc[ii][3] = fmaf(tv[ii].y, wv[1].w, acc[ii][3]);
                    acc[ii][0] = fmaf(tv[ii].z, wv[2].x, acc[ii][0]);
                    acc[ii][1] = fmaf(tv[ii].z, wv[2].y, acc[ii][1]);
                    acc[ii][2] = fmaf(tv[ii].z, wv[2].z, acc[ii][2]);
                    acc[ii][3] = fmaf(tv[ii].z, wv[2].w, acc[ii][3]);
                    acc[ii][0] = fmaf(tv[ii].w, wv[3].x, acc[ii][0]);
                    acc[ii][1] = fmaf(tv[ii].w, wv[3].y, acc[ii][1]);
                    acc[ii][2] = fmaf(tv[ii].w, wv[3].z, acc[ii][2]);
                    acc[ii][3] = fmaf(tv[ii].w, wv[3].w, acc[ii][3]);
                }
            }
            #pragma unroll
            for (int ii = 0; ii < 4; ii++) {
                const int i = i0 + ii;
                const float g = sGam[i];
                const float omg = 1.0f - g;
                float4 nv = __ldg(reinterpret_cast<const float4*>(nid + (c * 64 + i) * 64 + d0));
                float* hp = sH + i * 64 + d0;
                hp[0] = omg * hp[0] + g * tanhf(acc[ii][0] + sB2[d0 + 0] + nv.x);
                hp[1] = omg * hp[1] + g * tanhf(acc[ii][1] + sB2[d0 + 1] + nv.y);
                hp[2] = omg * hp[2] + g * tanhf(acc[ii][2] + sB2[d0 + 2] + nv.z);
                hp[3] = omg * hp[3] + g * tanhf(acc[ii][3] + sB2[d0 + 3] + nv.w);
            }
        }
        __syncthreads();

        // ---- readout (h_new) ----
        if (tid < 64) {
            float s = sH[sOp[0] * 64 + tid] + sH[sOp[1] * 64 + tid]
                    + sH[sOp[2] * 64 + tid] + sH[sOp[3] * 64 + tid];
            out[((b * Tt + t) * NCc + c) * 64 + tid] = s * 0.125f;  // (1/A)*A^-0.5
        }

        // ---- hebbian outer-product update + W decay: 4x4 tile/thread ----
        {
            const int j0 = lg * 4;
            float acc[4][4];
            #pragma unroll
            for (int ii = 0; ii < 4; ii++)
                #pragma unroll
                for (int jj = 0; jj < 4; jj++) acc[ii][jj] = 0.0f;

            for (int dq = 0; dq < 64; dq += 4) {
                float4 hi[4], hj[4];
                #pragma unroll
                for (int ii = 0; ii < 4; ii++)
                    hi[ii] = *reinterpret_cast<const float4*>(sH + (i0 + ii) * 64 + dq);
                #pragma unroll
                for (int jj = 0; jj < 4; jj++)
                    hj[jj] = *reinterpret_cast<const float4*>(sH + (j0 + jj) * 64 + dq);
                #pragma unroll
                for (int ii = 0; ii < 4; ii++)
                    #pragma unroll
                    for (int jj = 0; jj < 4; jj++) {
                        acc[ii][jj] = fmaf(hi[ii].x, hj[jj].x, acc[ii][jj]);
                        acc[ii][jj] = fmaf(hi[ii].y, hj[jj].y, acc[ii][jj]);
                        acc[ii][jj] = fmaf(hi[ii].z, hj[jj].z, acc[ii][jj]);
                        acc[ii][jj] = fmaf(hi[ii].w, hj[jj].w, acc[ii][jj]);
                    }
            }
            const float invd = 1.0f / 64.0f;   // (Dn^-0.5)^2
            #pragma unroll
            for (int ii = 0; ii < 4; ii++) {
                const int i = i0 + ii;
                const float hgv  = sHg[i];
                const float wdec = 1.0f - sWg[i];
                #pragma unroll
                for (int jj = 0; jj < 4; jj++) {
                    const int j = j0 + jj;
                    float v = (1.0f - hgv) * sHeb[i * 64 + j] + hgv * acc[ii][jj] * invd;
                    sHeb[i * 64 + j] = (i == j) ? 0.0f : v;
                    sW[i * 64 + j] *= wdec;
                }
            }
        }
        __syncthreads();
    }
}

extern "C" void kernel_launch(void* const* d_in, const int* in_sizes, int n_in,
                              void* d_out, int out_size) {
    const float* x    = (const float*)d_in[0];
    const float* h0   = (const float*)d_in[1];
    const float* W0   = (const float*)d_in[2];
    const float* heb0 = (const float*)d_in[3];
    const float* nid  = (const float*)d_in[4];
    const float* w1   = (const float*)d_in[5];
    const float* b1   = (const float*)d_in[6];
    const float* w2   = (const float*)d_in[7];
    const float* b2   = (const float*)d_in[8];
    const float* injw = (const float*)d_in[9];
    const float* injb = (const float*)d_in[10];
    const float* wdl  = (const float*)d_in[11];
    const float* dgl  = (const float*)d_in[12];
    const float* hdl  = (const float*)d_in[13];
    const int*   ipi  = (const int*)d_in[14];
    const int*   opi  = (const int*)d_in[15];
    float* out = (float*)d_out;

    const int smem_bytes = (4096 * 4 + 8192 + 64 + 256 + 256 + 64 + 64 + 64 + 128 + 64) * 4;
    cudaFuncSetAttribute(mg_main, cudaFuncAttributeMaxDynamicSharedMemorySize, smem_bytes);

    mg_transpose<<<32, 256>>>(w1, w2);
    mg_main<<<NCc * Bsz, 256, smem_bytes>>>(x, h0, W0, heb0, nid, injw, injb,
                                            b1, b2, wdl, dgl, hdl, ipi, opi, out);
}

// round 3
// speedup vs baseline: 1.0169x; 1.0169x over previous
#include <cuda_runtime.h>
#include <math.h>

#define Bsz   8
#define Tt    16
#define NCc   128
#define S64   68      // padded row stride for 64-wide matrices
#define S128  132     // padded row stride for 128-wide hidden

typedef unsigned long long u64;

// Pre-transposed MLP weights: g_w1T[d][h] = msg_w1[h][d], g_w2T[h][d] = msg_w2[d][h]
__device__ __align__(16) float g_w1T[64 * 128];
__device__ __align__(16) float g_w2T[128 * 64];

__global__ void mg_transpose(const float* __restrict__ w1,
                             const float* __restrict__ w2) {
    int tid = blockIdx.x * blockDim.x + threadIdx.x;
    if (tid < 128 * 64) {
        int h = tid / 64, d = tid % 64;         // w1 is [128][64]
        g_w1T[d * 128 + h] = w1[tid];
        int d2 = tid / 128, h2 = tid % 128;     // w2 is [64][128]
        g_w2T[h2 * 64 + d2] = w2[tid];
    }
}

// ---- packed f32x2 helpers ----
__device__ __forceinline__ u64 dup2(float a) {
    u64 r;
    asm("mov.b64 %0, {%1, %1};" : "=l"(r) : "r"(__float_as_uint(a)));
    return r;
}
__device__ __forceinline__ u64 fma2(u64 a, u64 b, u64 c) {
    u64 d;
    asm("fma.rn.f32x2 %0, %1, %2, %3;" : "=l"(d) : "l"(a), "l"(b), "l"(c));
    return d;
}
__device__ __forceinline__ void up2(u64 v, float& a, float& b) {
    unsigned int x, y;
    asm("mov.b64 {%0, %1}, %2;" : "=r"(x), "=r"(y) : "l"(v));
    a = __uint_as_float(x); b = __uint_as_float(y);
}

// One CTA (128 threads) per (b,c). All state SMEM-resident across the T loop.
__global__ __launch_bounds__(128, 2)
void mg_main(const float* __restrict__ x,     const float* __restrict__ h0,
             const float* __restrict__ W0,    const float* __restrict__ heb0,
             const float* __restrict__ nid,
             const float* __restrict__ injw,  const float* __restrict__ injb,
             const float* __restrict__ b1g,   const float* __restrict__ b2g,
             const float* __restrict__ wdl,   const float* __restrict__ dgl,
             const float* __restrict__ hdl,
             const int*   __restrict__ ipi,   const int*   __restrict__ opi,
             float* __restrict__ out) {
    extern __shared__ float sm[];
    float* sH    = sm;                 // 64*S64
    float* sW0   = sH    + 64 * S64;   // 64*S64
    float* sHeb  = sW0   + 64 * S64;   // 64*S64
    float* sM    = sHeb  + 64 * S64;   // 64*S64
    float* sBuf  = sM    + 64 * S64;   // 64*S128 (Wh with stride S64, then hidden with S128)
    float* sX    = sBuf  + 64 * S128;  // 64
    float* sInjB = sX    + 64;         // 256
    float* sGam  = sInjB + 256;        // 64
    float* sHg   = sGam  + 64;         // 64
    float* sOmWg = sHg   + 64;         // 64
    float* sDecW = sOmWg + 64;         // 64
    float* sB1   = sDecW + 64;         // 128
    float* sB2   = sB1   + 128;        // 64
    __shared__ int sIp[4], sOp[4];

    const int tid = threadIdx.x;
    const int c   = blockIdx.x / Bsz;   // consecutive blocks share c -> L2 reuse of cell params
    const int b   = blockIdx.x % Bsz;
    const long base = (long)(b * NCc + c) * 4096;

    // ---------------- setup ----------------
    if (tid < 64) {
        sGam[tid]  = 0.5f / (1.0f + expf(-dgl[c * 64 + tid]));
        sHg[tid]   = 0.5f / (1.0f + expf(-hdl[c * 64 + tid]));
        sOmWg[tid] = 1.0f - 0.5f / (1.0f + expf(-wdl[c * 64 + tid]));
        sDecW[tid] = 1.0f;
        sB2[tid]   = b2g[tid];
        sX[tid]    = x[((long)(b * Tt + 0) * NCc + c) * 64 + tid];
    }
    sB1[tid] = b1g[tid];
    for (int i = tid; i < 256; i += 128) sInjB[i] = injb[c * 256 + i];
    if (tid < 4) { sIp[tid] = ipi[c * 4 + tid]; sOp[tid] = opi[c * 4 + tid]; }
    for (int idx = tid; idx < 4096; idx += 128) {
        int r = idx >> 6, cl = idx & 63;
        sH[r * S64 + cl]   = h0[base + idx];
        sW0[r * S64 + cl]  = W0[base + idx];
        sHeb[r * S64 + cl] = heb0[base + idx];
    }
    __syncthreads();

    const int ti = tid >> 3, tj = tid & 7;     // 16 x 8 tiling (4x8 tiles)
    const int ri = tid >> 4, rj = tid & 15;    // 8 x 16 tiling (8x8 tiles, MLP1)

    for (int t = 0; t < Tt; ++t) {
        // ===== P1: inject matvec + scatter (thr 0-63) | Wh = pw*W0 + heb (thr 64-127) =====
        if (tid < 64) {
            const int d = tid;
            #pragma unroll
            for (int a = 0; a < 4; a++) {
                const float4* wrow = reinterpret_cast<const float4*>(
                    injw + (long)(c * 256 + a * 64 + d) * 64);
                float acc = sInjB[a * 64 + d];
                #pragma unroll 4
                for (int q = 0; q < 16; q++) {
                    float4 w  = __ldg(wrow + q);
                    float4 xv = *reinterpret_cast<const float4*>(sX + 4 * q);
                    acc = fmaf(w.x, xv.x, acc); acc = fmaf(w.y, xv.y, acc);
                    acc = fmaf(w.z, xv.z, acc); acc = fmaf(w.w, xv.w, acc);
                }
                sH[sIp[a] * S64 + d] += acc;   // column d exclusive to this thread
            }
        } else {
            const int r = tid - 64;
            const float pw = sDecW[r];
            const float4* w0r = reinterpret_cast<const float4*>(sW0 + r * S64);
            const float4* hbr = reinterpret_cast<const float4*>(sHeb + r * S64);
            float4*       whr = reinterpret_cast<float4*>(sBuf + r * S64);
            #pragma unroll 4
            for (int q = 0; q < 16; q++) {
                float4 w = w0r[q], hbv = hbr[q];
                float4 o;
                o.x = fmaf(pw, w.x, hbv.x); o.y = fmaf(pw, w.y, hbv.y);
                o.z = fmaf(pw, w.z, hbv.z); o.w = fmaf(pw, w.w, hbv.w);
                whr[q] = o;
            }
        }
        __syncthreads();

        // ===== P2: matmul-1  m = Wh @ h_in   (4x8 tiles, f32x2) =====
        {
            const int i0 = ti * 4, d0 = tj * 8;
            u64 acc[4][4];
            #pragma unroll
            for (int ii = 0; ii < 4; ii++)
                #pragma unroll
                for (int p = 0; p < 4; p++) acc[ii][p] = 0ULL;

            #pragma unroll 4
            for (int j = 0; j < 64; j += 4) {
                float4 wr[4]; ulonglong2 ha[4], hb[4];
                #pragma unroll
                for (int ii = 0; ii < 4; ii++)
                    wr[ii] = *reinterpret_cast<const float4*>(sBuf + (i0 + ii) * S64 + j);
                #pragma unroll
                for (int jj = 0; jj < 4; jj++) {
                    ha[jj] = *reinterpret_cast<const ulonglong2*>(sH + (j + jj) * S64 + d0);
                    hb[jj] = *reinterpret_cast<const ulonglong2*>(sH + (j + jj) * S64 + d0 + 4);
                }
                #pragma unroll
                for (int ii = 0; ii < 4; ii++) {
                    float w4[4] = {wr[ii].x, wr[ii].y, wr[ii].z, wr[ii].w};
                    #pragma unroll
                    for (int jj = 0; jj < 4; jj++) {
                        u64 wd = dup2(w4[jj]);
                        acc[ii][0] = fma2(wd, ha[jj].x, acc[ii][0]);
                        acc[ii][1] = fma2(wd, ha[jj].y, acc[ii][1]);
                        acc[ii][2] = fma2(wd, hb[jj].x, acc[ii][2]);
                        acc[ii][3] = fma2(wd, hb[jj].y, acc[ii][3]);
                    }
                }
            }
            #pragma unroll
            for (int ii = 0; ii < 4; ii++) {
                ulonglong2 v0; v0.x = acc[ii][0]; v0.y = acc[ii][1];
                ulonglong2 v1; v1.x = acc[ii][2]; v1.y = acc[ii][3];
                *reinterpret_cast<ulonglong2*>(sM + (i0 + ii) * S64 + d0)     = v0;
                *reinterpret_cast<ulonglong2*>(sM + (i0 + ii) * S64 + d0 + 4) = v1;
            }
        }
        __syncthreads();

        // ===== P3: MLP layer 1  hid = tanh(m @ w1T + b1)   (8x8 tiles, f32x2) =====
        {
            const int i0 = ri * 8, h0i = rj * 8;
            u64 acc[8][4];
            #pragma unroll
            for (int ii = 0; ii < 8; ii++)
                #pragma unroll
                for (int p = 0; p < 4; p++) acc[ii][p] = 0ULL;

            #pragma unroll 2
            for (int d = 0; d < 64; d += 4) {
                float4 mv[8]; ulonglong2 wA[4], wB[4];
                #pragma unroll
                for (int ii = 0; ii < 8; ii++)
                    mv[ii] = *reinterpret_cast<const float4*>(sM + (i0 + ii) * S64 + d);
                #pragma unroll
                for (int dd = 0; dd < 4; dd++) {
                    wA[dd] = __ldg(reinterpret_cast<const ulonglong2*>(g_w1T + (d + dd) * 128 + h0i));
                    wB[dd] = __ldg(reinterpret_cast<const ulonglong2*>(g_w1T + (d + dd) * 128 + h0i + 4));
                }
                #pragma unroll
                for (int ii = 0; ii < 8; ii++) {
                    float m4[4] = {mv[ii].x, mv[ii].y, mv[ii].z, mv[ii].w};
                    #pragma unroll
                    for (int dd = 0; dd < 4; dd++) {
                        u64 md = dup2(m4[dd]);
                        acc[ii][0] = fma2(md, wA[dd].x, acc[ii][0]);
                        acc[ii][1] = fma2(md, wA[dd].y, acc[ii][1]);
                        acc[ii][2] = fma2(md, wB[dd].x, acc[ii][2]);
                        acc[ii][3] = fma2(md, wB[dd].y, acc[ii][3]);
                    }
                }
            }
            #pragma unroll
            for (int ii = 0; ii < 8; ii++) {
                float v[8];
                up2(acc[ii][0], v[0], v[1]); up2(acc[ii][1], v[2], v[3]);
                up2(acc[ii][2], v[4], v[5]); up2(acc[ii][3], v[6], v[7]);
                float4 o0, o1;
                o0.x = tanhf(v[0] + sB1[h0i + 0]); o0.y = tanhf(v[1] + sB1[h0i + 1]);
                o0.z = tanhf(v[2] + sB1[h0i + 2]); o0.w = tanhf(v[3] + sB1[h0i + 3]);
                o1.x = tanhf(v[4] + sB1[h0i + 4]); o1.y = tanhf(v[5] + sB1[h0i + 5]);
                o1.z = tanhf(v[6] + sB1[h0i + 6]); o1.w = tanhf(v[7] + sB1[h0i + 7]);
                *reinterpret_cast<float4*>(sBuf + (i0 + ii) * S128 + h0i)     = o0;
                *reinterpret_cast<float4*>(sBuf + (i0 + ii) * S128 + h0i + 4) = o1;
            }
        }
        __syncthreads();

        // ===== P4: MLP layer 2 + gated state update (4x8 tiles, f32x2, sH in place) =====
        {
            const int i0 = ti * 4, d0 = tj * 8;
            u64 acc[4][4];
            #pragma unroll
            for (int ii = 0; ii < 4; ii++)
                #pragma unroll
                for (int p = 0; p < 4; p++) acc[ii][p] = 0ULL;

            #pragma unroll 4
            for (int h = 0; h < 128; h += 4) {
                float4 tv[4]; ulonglong2 wA[4], wB[4];
                #pragma unroll
                for (int ii = 0; ii < 4; ii++)
                    tv[ii] = *reinterpret_cast<const float4*>(sBuf + (i0 + ii) * S128 + h);
                #pragma unroll
                for (int hh = 0; hh < 4; hh++) {
                    wA[hh] = __ldg(reinterpret_cast<const ulonglong2*>(g_w2T + (h + hh) * 64 + d0));
                    wB[hh] = __ldg(reinterpret_cast<const ulonglong2*>(g_w2T + (h + hh) * 64 + d0 + 4));
                }
                #pragma unroll
                for (int ii = 0; ii < 4; ii++) {
                    float t4[4] = {tv[ii].x, tv[ii].y, tv[ii].z, tv[ii].w};
                    #pragma unroll
                    for (int hh = 0; hh < 4; hh++) {
                        u64 td = dup2(t4[hh]);
                        acc[ii][0] = fma2(td, wA[hh].x, acc[ii][0]);
                        acc[ii][1] = fma2(td, wA[hh].y, acc[ii][1]);
                        acc[ii][2] = fma2(td, wB[hh].x, acc[ii][2]);
                        acc[ii][3] = fma2(td, wB[hh].y, acc[ii][3]);
                    }
                }
            }
            #pragma unroll
            for (int ii = 0; ii < 4; ii++) {
                const int i = i0 + ii;
                const float g = sGam[i], omg = 1.0f - g;
                float4 n0 = __ldg(reinterpret_cast<const float4*>(nid + ((long)c * 64 + i) * 64 + d0));
                float4 n1 = __ldg(reinterpret_cast<const float4*>(nid + ((long)c * 64 + i) * 64 + d0 + 4));
                float v[8];
                up2(acc[ii][0], v[0], v[1]); up2(acc[ii][1], v[2], v[3]);
                up2(acc[ii][2], v[4], v[5]); up2(acc[ii][3], v[6], v[7]);
                float4 hc0 = *reinterpret_cast<const float4*>(sH + i * S64 + d0);
                float4 hc1 = *reinterpret_cast<const float4*>(sH + i * S64 + d0 + 4);
                float4 o0, o1;
                o0.x = omg * hc0.x + g * tanhf(v[0] + sB2[d0 + 0] + n0.x);
                o0.y = omg * hc0.y + g * tanhf(v[1] + sB2[d0 + 1] + n0.y);
                o0.z = omg * hc0.z + g * tanhf(v[2] + sB2[d0 + 2] + n0.z);
                o0.w = omg * hc0.w + g * tanhf(v[3] + sB2[d0 + 3] + n0.w);
                o1.x = omg * hc1.x + g * tanhf(v[4] + sB2[d0 + 4] + n1.x);
                o1.y = omg * hc1.y + g * tanhf(v[5] + sB2[d0 + 5] + n1.y);
                o1.z = omg * hc1.z + g * tanhf(v[6] + sB2[d0 + 6] + n1.z);
                o1.w = omg * hc1.w + g * tanhf(v[7] + sB2[d0 + 7] + n1.w);
                *reinterpret_cast<float4*>(sH + i * S64 + d0)     = o0;
                *reinterpret_cast<float4*>(sH + i * S64 + d0 + 4) = o1;
            }
        }
        __syncthreads();

        // ===== P5: readout + hebbian update + pw decay + x prefetch =====
        if (tid < 64) {
            float s = sH[sOp[0] * S64 + tid] + sH[sOp[1] * S64 + tid]
                    + sH[sOp[2] * S64 + tid] + sH[sOp[3] * S64 + tid];
            out[((long)(b * Tt + t) * NCc + c) * 64 + tid] = s * 0.125f;
        }
        {
            const int i0 = ti * 4, j0 = tj * 8;
            float acc[4][8];
            #pragma unroll
            for (int ii = 0; ii < 4; ii++)
                #pragma unroll
                for (int jj = 0; jj < 8; jj++) acc[ii][jj] = 0.0f;

            #pragma unroll 4
            for (int dq = 0; dq < 64; dq += 4) {
                float4 hi[4], hj[8];
                #pragma unroll
                for (int ii = 0; ii < 4; ii++)
                    hi[ii] = *reinterpret_cast<const float4*>(sH + (i0 + ii) * S64 + dq);
                #pragma unroll
                for (int jj = 0; jj < 8; jj++)
                    hj[jj] = *reinterpret_cast<const float4*>(sH + (j0 + jj) * S64 + dq);
                #pragma unroll
                for (int ii = 0; ii < 4; ii++)
                    #pragma unroll
                    for (int jj = 0; jj < 8; jj++) {
                        acc[ii][jj] = fmaf(hi[ii].x, hj[jj].x, acc[ii][jj]);
                        acc[ii][jj] = fmaf(hi[ii].y, hj[jj].y, acc[ii][jj]);
                        acc[ii][jj] = fmaf(hi[ii].z, hj[jj].z, acc[ii][jj]);
                        acc[ii][jj] = fmaf(hi[ii].w, hj[jj].w, acc[ii][jj]);
                    }
            }
            #pragma unroll
            for (int ii = 0; ii < 4; ii++) {
                const int i = i0 + ii;
                const float hgv = sHg[i], omh = 1.0f - hgv, sc = hgv * (1.0f / 64.0f);
                float4 e0 = *reinterpret_cast<const float4*>(sHeb + i * S64 + j0);
                float4 e1 = *reinterpret_cast<const float4*>(sHeb + i * S64 + j0 + 4);
                float v[8];
                v[0] = omh * e0.x + sc * acc[ii][0]; v[1] = omh * e0.y + sc * acc[ii][1];
                v[2] = omh * e0.z + sc * acc[ii][2]; v[3] = omh * e0.w + sc * acc[ii][3];
                v[4] = omh * e1.x + sc * acc[ii][4]; v[5] = omh * e1.y + sc * acc[ii][5];
                v[6] = omh * e1.z + sc * acc[ii][6]; v[7] = omh * e1.w + sc * acc[ii][7];
                #pragma unroll
                for (int jj = 0; jj < 8; jj++) if (i == j0 + jj) v[jj] = 0.0f;
                float4 o0 = make_float4(v[0], v[1], v[2], v[3]);
                float4 o1 = make_float4(v[4], v[5], v[6], v[7]);
                *reinterpret_cast<float4*>(sHeb + i * S64 + j0)     = o0;
                *reinterpret_cast<float4*>(sHeb + i * S64 + j0 + 4) = o1;
            }
        }
        if (tid < 64) {
            sDecW[tid] *= sOmWg[tid];
            if (t + 1 < Tt)
                sX[tid] = x[((long)(b * Tt + t + 1) * NCc + c) * 64 + tid];
        }
        __syncthreads();
    }
}

extern "C" void kernel_launch(void* const* d_in, const int* in_sizes, int n_in,
                              void* d_out, int out_size) {
    const float* x    = (const float*)d_in[0];
    const float* h0   = (const float*)d_in[1];
    const float* W0   = (const float*)d_in[2];
    const float* heb0 = (const float*)d_in[3];
    const float* nid  = (const float*)d_in[4];
    const float* w1   = (const float*)d_in[5];
    const float* b1   = (const float*)d_in[6];
    const float* w2   = (const float*)d_in[7];
    const float* b2   = (const float*)d_in[8];
    const float* injw = (const float*)d_in[9];
    const float* injb = (const float*)d_in[10];
    const float* wdl  = (const float*)d_in[11];
    const float* dgl  = (const float*)d_in[12];
    const float* hdl  = (const float*)d_in[13];
    const int*   ipi  = (const int*)d_in[14];
    const int*   opi  = (const int*)d_in[15];
    float* out = (float*)d_out;

    const int smem_floats = 64 * S64 * 4 + 64 * S128 + 64 + 256 + 64 * 4 + 128 + 64;
    const int smem_bytes  = smem_floats * 4;
    cudaFuncSetAttribute(mg_main, cudaFuncAttributeMaxDynamicSharedMemorySize, smem_bytes);

    mg_transpose<<<32, 256>>>(w1, w2);
    mg_main<<<NCc * Bsz, 128, smem_bytes>>>(x, h0, W0, heb0, nid, injw, injb,
                                            b1, b2, wdl, dgl, hdl, ipi, opi, out);
}

// round 4
// speedup vs baseline: 1.0169x; 1.0000x over previous
#include <cuda_runtime.h>
#include <math.h>

#define Bsz   8
#define Tt    16
#define NCc   128
#define S64   68      // padded row stride for 64-wide matrices
#define S128  132     // padded row stride for 128-wide hidden

typedef unsigned long long u64;

// Pre-transposed MLP weights: g_w1T[d][h] = msg_w1[h][d], g_w2T[h][d] = msg_w2[d][h]
__device__ __align__(16) float g_w1T[64 * 128];
__device__ __align__(16) float g_w2T[128 * 64];

__global__ void mg_transpose(const float* __restrict__ w1,
                             const float* __restrict__ w2) {
    int tid = blockIdx.x * blockDim.x + threadIdx.x;
    if (tid < 128 * 64) {
        int h = tid / 64, d = tid % 64;         // w1 is [128][64]
        g_w1T[d * 128 + h] = w1[tid];
        int d2 = tid / 128, h2 = tid % 128;     // w2 is [64][128]
        g_w2T[h2 * 64 + d2] = w2[tid];
    }
}

// ---- packed f32x2 helpers ----
__device__ __forceinline__ u64 dup2(float a) {
    u64 r;
    asm("mov.b64 %0, {%1, %1};" : "=l"(r) : "r"(__float_as_uint(a)));
    return r;
}
__device__ __forceinline__ u64 fma2(u64 a, u64 b, u64 c) {
    u64 d;
    asm("fma.rn.f32x2 %0, %1, %2, %3;" : "=l"(d) : "l"(a), "l"(b), "l"(c));
    return d;
}
__device__ __forceinline__ void up2(u64 v, float& a, float& b) {
    unsigned int x, y;
    asm("mov.b64 {%0, %1}, %2;" : "=r"(x), "=r"(y) : "l"(v));
    a = __uint_as_float(x); b = __uint_as_float(y);
}

// One CTA (128 threads) per (b,c). All state SMEM-resident across the T loop.
__global__ __launch_bounds__(128, 2)
void mg_main(const float* __restrict__ x,     const float* __restrict__ h0,
             const float* __restrict__ W0,    const float* __restrict__ heb0,
             const float* __restrict__ nid,
             const float* __restrict__ injw,  const float* __restrict__ injb,
             const float* __restrict__ b1g,   const float* __restrict__ b2g,
             const float* __restrict__ wdl,   const float* __restrict__ dgl,
             const float* __restrict__ hdl,
             const int*   __restrict__ ipi,   const int*   __restrict__ opi,
             float* __restrict__ out) {
    extern __shared__ float sm[];
    float* sH    = sm;                 // 64*S64
    float* sW0   = sH    + 64 * S64;   // 64*S64
    float* sHeb  = sW0   + 64 * S64;   // 64*S64
    float* sM    = sHeb  + 64 * S64;   // 64*S64
    float* sBuf  = sM    + 64 * S64;   // 64*S128 (Wh with stride S64, then hidden with S128)
    float* sX    = sBuf  + 64 * S128;  // 64
    float* sInjB = sX    + 64;         // 256
    float* sGam  = sInjB + 256;        // 64
    float* sHg   = sGam  + 64;         // 64
    float* sOmWg = sHg   + 64;         // 64
    float* sDecW = sOmWg + 64;         // 64
    float* sB1   = sDecW + 64;         // 128
    float* sB2   = sB1   + 128;        // 64
    __shared__ int sIp[4], sOp[4];

    const int tid = threadIdx.x;
    const int c   = blockIdx.x / Bsz;   // consecutive blocks share c -> L2 reuse of cell params
    const int b   = blockIdx.x % Bsz;
    const long base = (long)(b * NCc + c) * 4096;

    // ---------------- setup ----------------
    if (tid < 64) {
        sGam[tid]  = 0.5f / (1.0f + expf(-dgl[c * 64 + tid]));
        sHg[tid]   = 0.5f / (1.0f + expf(-hdl[c * 64 + tid]));
        sOmWg[tid] = 1.0f - 0.5f / (1.0f + expf(-wdl[c * 64 + tid]));
        sDecW[tid] = 1.0f;
        sB2[tid]   = b2g[tid];
        sX[tid]    = x[((long)(b * Tt + 0) * NCc + c) * 64 + tid];
    }
    sB1[tid] = b1g[tid];
    for (int i = tid; i < 256; i += 128) sInjB[i] = injb[c * 256 + i];
    if (tid < 4) { sIp[tid] = ipi[c * 4 + tid]; sOp[tid] = opi[c * 4 + tid]; }
    for (int idx = tid; idx < 4096; idx += 128) {
        int r = idx >> 6, cl = idx & 63;
        sH[r * S64 + cl]   = h0[base + idx];
        sW0[r * S64 + cl]  = W0[base + idx];
        sHeb[r * S64 + cl] = heb0[base + idx];
    }
    __syncthreads();

    const int ti = tid >> 3, tj = tid & 7;     // 16 x 8 tiling (4x8 tiles)
    const int ri = tid >> 4, rj = tid & 15;    // 8 x 16 tiling (8x8 tiles, MLP1)

    for (int t = 0; t < Tt; ++t) {
        // ===== P1: inject matvec + scatter (thr 0-63) | Wh = pw*W0 + heb (thr 64-127) =====
        if (tid < 64) {
            const int d = tid;
            #pragma unroll
            for (int a = 0; a < 4; a++) {
                const float4* wrow = reinterpret_cast<const float4*>(
                    injw + (long)(c * 256 + a * 64 + d) * 64);
                float acc = sInjB[a * 64 + d];
                #pragma unroll 4
                for (int q = 0; q < 16; q++) {
                    float4 w  = __ldg(wrow + q);
                    float4 xv = *reinterpret_cast<const float4*>(sX + 4 * q);
                    acc = fmaf(w.x, xv.x, acc); acc = fmaf(w.y, xv.y, acc);
                    acc = fmaf(w.z, xv.z, acc); acc = fmaf(w.w, xv.w, acc);
                }
                sH[sIp[a] * S64 + d] += acc;   // column d exclusive to this thread
            }
        } else {
            const int r = tid - 64;
            const float pw = sDecW[r];
            const float4* w0r = reinterpret_cast<const float4*>(sW0 + r * S64);
            const float4* hbr = reinterpret_cast<const float4*>(sHeb + r * S64);
            float4*       whr = reinterpret_cast<float4*>(sBuf + r * S64);
            #pragma unroll 4
            for (int q = 0; q < 16; q++) {
                float4 w = w0r[q], hbv = hbr[q];
                float4 o;
                o.x = fmaf(pw, w.x, hbv.x); o.y = fmaf(pw, w.y, hbv.y);
                o.z = fmaf(pw, w.z, hbv.z); o.w = fmaf(pw, w.w, hbv.w);
                whr[q] = o;
            }
        }
        __syncthreads();

        // ===== P2: matmul-1  m = Wh @ h_in   (4x8 tiles, f32x2) =====
        {
            const int i0 = ti * 4, d0 = tj * 8;
            u64 acc[4][4];
            #pragma unroll
            for (int ii = 0; ii < 4; ii++)
                #pragma unroll
                for (int p = 0; p < 4; p++) acc[ii][p] = 0ULL;

            #pragma unroll 4
            for (int j = 0; j < 64; j += 4) {
                float4 wr[4]; ulonglong2 ha[4], hb[4];
                #pragma unroll
                for (int ii = 0; ii < 4; ii++)
                    wr[ii] = *reinterpret_cast<const float4*>(sBuf + (i0 + ii) * S64 + j);
                #pragma unroll
                for (int jj = 0; jj < 4; jj++) {
                    ha[jj] = *reinterpret_cast<const ulonglong2*>(sH + (j + jj) * S64 + d0);
                    hb[jj] = *reinterpret_cast<const ulonglong2*>(sH + (j + jj) * S64 + d0 + 4);
                }
                #pragma unroll
                for (int ii = 0; ii < 4; ii++) {
                    float w4[4] = {wr[ii].x, wr[ii].y, wr[ii].z, wr[ii].w};
                    #pragma unroll
                    for (int jj = 0; jj < 4; jj++) {
                        u64 wd = dup2(w4[jj]);
                        acc[ii][0] = fma2(wd, ha[jj].x, acc[ii][0]);
                        acc[ii][1] = fma2(wd, ha[jj].y, acc[ii][1]);
                        acc[ii][2] = fma2(wd, hb[jj].x, acc[ii][2]);
                        acc[ii][3] = fma2(wd, hb[jj].y, acc[ii][3]);
                    }
                }
            }
            #pragma unroll
            for (int ii = 0; ii < 4; ii++) {
                ulonglong2 v0; v0.x = acc[ii][0]; v0.y = acc[ii][1];
                ulonglong2 v1; v1.x = acc[ii][2]; v1.y = acc[ii][3];
                *reinterpret_cast<ulonglong2*>(sM + (i0 + ii) * S64 + d0)     = v0;
                *reinterpret_cast<ulonglong2*>(sM + (i0 + ii) * S64 + d0 + 4) = v1;
            }
        }
        __syncthreads();

        // ===== P3: MLP layer 1  hid = tanh(m @ w1T + b1)   (8x8 tiles, f32x2) =====
        {
            const int i0 = ri * 8, h0i = rj * 8;
            u64 acc[8][4];
            #pragma unroll
            for (int ii = 0; ii < 8; ii++)
                #pragma unroll
                for (int p = 0; p < 4; p++) acc[ii][p] = 0ULL;

            #pragma unroll 2
            for (int d = 0; d < 64; d += 4) {
                float4 mv[8]; ulonglong2 wA[4], wB[4];
                #pragma unroll
                for (int ii = 0; ii < 8; ii++)
                    mv[ii] = *reinterpret_cast<const float4*>(sM + (i0 + ii) * S64 + d);
                #pragma unroll
                for (int dd = 0; dd < 4; dd++) {
                    wA[dd] = __ldg(reinterpret_cast<const ulonglong2*>(g_w1T + (d + dd) * 128 + h0i));
                    wB[dd] = __ldg(reinterpret_cast<const ulonglong2*>(g_w1T + (d + dd) * 128 + h0i + 4));
                }
                #pragma unroll
                for (int ii = 0; ii < 8; ii++) {
                    float m4[4] = {mv[ii].x, mv[ii].y, mv[ii].z, mv[ii].w};
                    #pragma unroll
                    for (int dd = 0; dd < 4; dd++) {
                        u64 md = dup2(m4[dd]);
                        acc[ii][0] = fma2(md, wA[dd].x, acc[ii][0]);
                        acc[ii][1] = fma2(md, wA[dd].y, acc[ii][1]);
                        acc[ii][2] = fma2(md, wB[dd].x, acc[ii][2]);
                        acc[ii][3] = fma2(md, wB[dd].y, acc[ii][3]);
                    }
                }
            }
            #pragma unroll
            for (int ii = 0; ii < 8; ii++) {
                float v[8];
                up2(acc[ii][0], v[0], v[1]); up2(acc[ii][1], v[2], v[3]);
                up2(acc[ii][2], v[4], v[5]); up2(acc[ii][3], v[6], v[7]);
                float4 o0, o1;
                o0.x = tanhf(v[0] + sB1[h0i + 0]); o0.y = tanhf(v[1] + sB1[h0i + 1]);
                o0.z = tanhf(v[2] + sB1[h0i + 2]); o0.w = tanhf(v[3] + sB1[h0i + 3]);
                o1.x = tanhf(v[4] + sB1[h0i + 4]); o1.y = tanhf(v[5] + sB1[h0i + 5]);
                o1.z = tanhf(v[6] + sB1[h0i + 6]); o1.w = tanhf(v[7] + sB1[h0i + 7]);
                *reinterpret_cast<float4*>(sBuf + (i0 + ii) * S128 + h0i)     = o0;
                *reinterpret_cast<float4*>(sBuf + (i0 + ii) * S128 + h0i + 4) = o1;
            }
        }
        __syncthreads();

        // ===== P4: MLP layer 2 + gated state update (4x8 tiles, f32x2, sH in place) =====
        {
            const int i0 = ti * 4, d0 = tj * 8;
            u64 acc[4][4];
            #pragma unroll
            for (int ii = 0; ii < 4; ii++)
                #pragma unroll
                for (int p = 0; p < 4; p++) acc[ii][p] = 0ULL;

            #pragma unroll 4
            for (int h = 0; h < 128; h += 4) {
                float4 tv[4]; ulonglong2 wA[4], wB[4];
                #pragma unroll
                for (int ii = 0; ii < 4; ii++)
                    tv[ii] = *reinterpret_cast<const float4*>(sBuf + (i0 + ii) * S128 + h);
                #pragma unroll
                for (int hh = 0; hh < 4; hh++) {
                    wA[hh] = __ldg(reinterpret_cast<const ulonglong2*>(g_w2T + (h + hh) * 64 + d0));
                    wB[hh] = __ldg(reinterpret_cast<const ulonglong2*>(g_w2T + (h + hh) * 64 + d0 + 4));
                }
                #pragma unroll
                for (int ii = 0; ii < 4; ii++) {
                    float t4[4] = {tv[ii].x, tv[ii].y, tv[ii].z, tv[ii].w};
                    #pragma unroll
                    for (int hh = 0; hh < 4; hh++) {
                        u64 td = dup2(t4[hh]);
                        acc[ii][0] = fma2(td, wA[hh].x, acc[ii][0]);
                        acc[ii][1] = fma2(td, wA[hh].y, acc[ii][1]);
                        acc[ii][2] = fma2(td, wB[hh].x, acc[ii][2]);
                        acc[ii][3] = fma2(td, wB[hh].y, acc[ii][3]);
                    }
                }
            }
            #pragma unroll
            for (int ii = 0; ii < 4; ii++) {
                const int i = i0 + ii;
                const float g = sGam[i], omg = 1.0f - g;
                float4 n0 = __ldg(reinterpret_cast<const float4*>(nid + ((long)c * 64 + i) * 64 + d0));
                float4 n1 = __ldg(reinterpret_cast<const float4*>(nid + ((long)c * 64 + i) * 64 + d0 + 4));
                float v[8];
                up2(acc[ii][0], v[0], v[1]); up2(acc[ii][1], v[2], v[3]);
                up2(acc[ii][2], v[4], v[5]); up2(acc[ii][3], v[6], v[7]);
                float4 hc0 = *reinterpret_cast<const float4*>(sH + i * S64 + d0);
                float4 hc1 = *reinterpret_cast<const float4*>(sH + i * S64 + d0 + 4);
                float4 o0, o1;
                o0.x = omg * hc0.x + g * tanhf(v[0] + sB2[d0 + 0] + n0.x);
                o0.y = omg * hc0.y + g * tanhf(v[1] + sB2[d0 + 1] + n0.y);
                o0.z = omg * hc0.z + g * tanhf(v[2] + sB2[d0 + 2] + n0.z);
                o0.w = omg * hc0.w + g * tanhf(v[3] + sB2[d0 + 3] + n0.w);
                o1.x = omg * hc1.x + g * tanhf(v[4] + sB2[d0 + 4] + n1.x);
                o1.y = omg * hc1.y + g * tanhf(v[5] + sB2[d0 + 5] + n1.y);
                o1.z = omg * hc1.z + g * tanhf(v[6] + sB2[d0 + 6] + n1.z);
                o1.w = omg * hc1.w + g * tanhf(v[7] + sB2[d0 + 7] + n1.w);
                *reinterpret_cast<float4*>(sH + i * S64 + d0)     = o0;
                *reinterpret_cast<float4*>(sH + i * S64 + d0 + 4) = o1;
            }
        }
        __syncthreads();

        // ===== P5: readout + hebbian update + pw decay + x prefetch =====
        if (tid < 64) {
            float s = sH[sOp[0] * S64 + tid] + sH[sOp[1] * S64 + tid]
                    + sH[sOp[2] * S64 + tid] + sH[sOp[3] * S64 + tid];
            out[((long)(b * Tt + t) * NCc + c) * 64 + tid] = s * 0.125f;
        }
        {
            const int i0 = ti * 4, j0 = tj * 8;
            float acc[4][8];
            #pragma unroll
            for (int ii = 0; ii < 4; ii++)
                #pragma unroll
                for (int jj = 0; jj < 8; jj++) acc[ii][jj] = 0.0f;

            #pragma unroll 4
            for (int dq = 0; dq < 64; dq += 4) {
                float4 hi[4], hj[8];
                #pragma unroll
                for (int ii = 0; ii < 4; ii++)
                    hi[ii] = *reinterpret_cast<const float4*>(sH + (i0 + ii) * S64 + dq);
                #pragma unroll
                for (int jj = 0; jj < 8; jj++)
                    hj[jj] = *reinterpret_cast<const float4*>(sH + (j0 + jj) * S64 + dq);
                #pragma unroll
                for (int ii = 0; ii < 4; ii++)
                    #pragma unroll
                    for (int jj = 0; jj < 8; jj++) {
                        acc[ii][jj] = fmaf(hi[ii].x, hj[jj].x, acc[ii][jj]);
                        acc[ii][jj] = fmaf(hi[ii].y, hj[jj].y, acc[ii][jj]);
                        acc[ii][jj] = fmaf(hi[ii].z, hj[jj].z, acc[ii][jj]);
                        acc[ii][jj] = fmaf(hi[ii].w, hj[jj].w, acc[ii][jj]);
                    }
            }
            #pragma unroll
            for (int ii = 0; ii < 4; ii++) {
                const int i = i0 + ii;
                const float hgv = sHg[i], omh = 1.0f - hgv, sc = hgv * (1.0f / 64.0f);
                float4 e0 = *reinterpret_cast<const float4*>(sHeb + i * S64 + j0);
                float4 e1 = *reinterpret_cast<const float4*>(sHeb + i * S64 + j0 + 4);
                float v[8];
                v[0] = omh * e0.x + sc * acc[ii][0]; v[1] = omh * e0.y + sc * acc[ii][1];
                v[2] = omh * e0.z + sc * acc[ii][2]; v[3] = omh * e0.w + sc * acc[ii][3];
                v[4] = omh * e1.x + sc * acc[ii][4]; v[5] = omh * e1.y + sc * acc[ii][5];
                v[6] = omh * e1.z + sc * acc[ii][6]; v[7] = omh * e1.w + sc * acc[ii][7];
                #pragma unroll
                for (int jj = 0; jj < 8; jj++) if (i == j0 + jj) v[jj] = 0.0f;
                float4 o0 = make_float4(v[0], v[1], v[2], v[3]);
                float4 o1 = make_float4(v[4], v[5], v[6], v[7]);
                *reinterpret_cast<float4*>(sHeb + i * S64 + j0)     = o0;
                *reinterpret_cast<float4*>(sHeb + i * S64 + j0 + 4) = o1;
            }
        }
        if (tid < 64) {
            sDecW[tid] *= sOmWg[tid];
            if (t + 1 < Tt)
                sX[tid] = x[((long)(b * Tt + t + 1) * NCc + c) * 64 + tid];
        }
        __syncthreads();
    }
}

extern "C" void kernel_launch(void* const* d_in, const int* in_sizes, int n_in,
                              void* d_out, int out_size) {
    const float* x    = (const float*)d_in[0];
    const float* h0   = (const float*)d_in[1];
    const float* W0   = (const float*)d_in[2];
    const float* heb0 = (const float*)d_in[3];
    const float* nid  = (const float*)d_in[4];
    const float* w1   = (const float*)d_in[5];
    const float* b1   = (const float*)d_in[6];
    const float* w2   = (const float*)d_in[7];
    const float* b2   = (const float*)d_in[8];
    const float* injw = (const float*)d_in[9];
    const float* injb = (const float*)d_in[10];
    const float* wdl  = (const float*)d_in[11];
    const float* dgl  = (const float*)d_in[12];
    const float* hdl  = (const float*)d_in[13];
    const int*   ipi  = (const int*)d_in[14];
    const int*   opi  = (const int*)d_in[15];
    float* out = (float*)d_out;

    const int smem_floats = 64 * S64 * 4 + 64 * S128 + 64 + 256 + 64 * 4 + 128 + 64;
    const int smem_bytes  = smem_floats * 4;
    cudaFuncSetAttribute(mg_main, cudaFuncAttributeMaxDynamicSharedMemorySize, smem_bytes);

    mg_transpose<<<32, 256>>>(w1, w2);
    mg_main<<<NCc * Bsz, 128, smem_bytes>>>(x, h0, W0, heb0, nid, injw, injb,
                                            b1, b2, wdl, dgl, hdl, ipi, opi, out);
}